// round 16
// baseline (speedup 1.0000x reference)
#include <cuda_runtime.h>
#include <cuda_bf16.h>
#include <cuda_fp16.h>
#include <math.h>
#include <stdint.h>

#define Bv 8
#define Nv 1024
#define Fv 256
#define Hv 8
#define Ev 64
#define SCALING 0.125f

// ---------------- operand buffers (static scratch) ----------------
__device__ __half g_qhi[Hv * Bv * Nv * Ev];
__device__ __half g_qlo[Hv * Bv * Nv * Ev];
__device__ __half g_khi[Hv * Bv * Nv * Ev];
__device__ __half g_klo[Hv * Bv * Nv * Ev];
__device__ __half g_vthi[Hv * Bv * Ev * Nv];          // [hb][e][n] transposed

__device__ __nv_bfloat16 g_xhi[Bv * Nv * Fv];
__device__ __nv_bfloat16 g_xlo[Bv * Nv * Fv];
__device__ __nv_bfloat16 g_wthi[3 * Hv * Ev * Fv];    // [z][h][e][f]
__device__ __nv_bfloat16 g_wtlo[3 * Hv * Ev * Fv];

// attn work queue + cross-CTA combine state
__device__ unsigned int g_tile_ctr;
__device__ float        g_zpart[2048 * 128];          // per-subtile partial Z
__device__ int          g_zctr[512];                  // per-tile arrival count

// ---------------- helpers ----------------
__device__ __forceinline__ uint32_t smem_to_u32(const void* p) {
    uint32_t a;
    asm("{ .reg .u64 tmp; cvta.to.shared.u64 tmp, %1; cvt.u32.u64 %0, tmp; }"
        : "=r"(a) : "l"(p));
    return a;
}

__device__ __forceinline__ void cp16(uint32_t dst, const void* src) {
    asm volatile("cp.async.cg.shared.global [%0], [%1], 16;"
                 :: "r"(dst), "l"(src));
}
#define CP_COMMIT() asm volatile("cp.async.commit_group;")
#define CP_WAIT1()  asm volatile("cp.async.wait_group 1;")
#define CP_WAIT0()  asm volatile("cp.async.wait_group 0;")

__device__ __forceinline__ void ldsm4(uint32_t* r, uint32_t addr) {
    asm volatile("ldmatrix.sync.aligned.m8n8.x4.shared.b16 {%0,%1,%2,%3}, [%4];"
                 : "=r"(r[0]), "=r"(r[1]), "=r"(r[2]), "=r"(r[3]) : "r"(addr));
}

__device__ __forceinline__ void mma_bf16(float* d, const uint32_t* a, const uint32_t* b) {
    asm volatile(
        "mma.sync.aligned.m16n8k16.row.col.f32.bf16.bf16.f32 "
        "{%0,%1,%2,%3}, {%4,%5,%6,%7}, {%8,%9}, {%0,%1,%2,%3};"
        : "+f"(d[0]), "+f"(d[1]), "+f"(d[2]), "+f"(d[3])
        : "r"(a[0]), "r"(a[1]), "r"(a[2]), "r"(a[3]), "r"(b[0]), "r"(b[1]));
}

__device__ __forceinline__ void mma_f16(float* d, const uint32_t* a, const uint32_t* b) {
    asm volatile(
        "mma.sync.aligned.m16n8k16.row.col.f32.f16.f16.f32 "
        "{%0,%1,%2,%3}, {%4,%5,%6,%7}, {%8,%9}, {%0,%1,%2,%3};"
        : "+f"(d[0]), "+f"(d[1]), "+f"(d[2]), "+f"(d[3])
        : "r"(a[0]), "r"(a[1]), "r"(a[2]), "r"(a[3]), "r"(b[0]), "r"(b[1]));
}

__device__ __forceinline__ void split2(float a, float b, uint32_t& hi, uint32_t& lo) {
    __nv_bfloat162 h2 = __floats2bfloat162_rn(a, b);
    float ha = __low2float(h2), hb = __high2float(h2);
    __nv_bfloat162 l2 = __floats2bfloat162_rn(a - ha, b - hb);
    hi = *reinterpret_cast<uint32_t*>(&h2);
    lo = *reinterpret_cast<uint32_t*>(&l2);
}

__device__ __forceinline__ void split2h(float a, float b, uint32_t& hi, uint32_t& lo) {
    __half2 h2 = __floats2half2_rn(a, b);
    float2 hf = __half22float2(h2);
    __half2 l2 = __floats2half2_rn(a - hf.x, b - hf.y);
    hi = *reinterpret_cast<uint32_t*>(&h2);
    lo = *reinterpret_cast<uint32_t*>(&l2);
}

__device__ __forceinline__ uint32_t pack2h(float a, float b) {
    __half2 h2 = __floats2half2_rn(a, b);
    return *reinterpret_cast<uint32_t*>(&h2);
}

// ---------------------------------------------------------------------------
// Kernel 0: merged input splits + zero O-region of out + reset queue/counters
// ---------------------------------------------------------------------------
__global__ __launch_bounds__(256) void split_inputs_kernel(
    const float* __restrict__ x,
    const float* __restrict__ Wq, const float* __restrict__ Wk,
    const float* __restrict__ Wv,
    float* __restrict__ out_zero)
{
    __shared__ float ws[64][65];
    const int t = threadIdx.x;
    if (blockIdx.x == 0 && t == 0) g_tile_ctr = 0;

    if (blockIdx.x < 2048) {
        int idx = blockIdx.x * 256 + t;
        float4 v = reinterpret_cast<const float4*>(x)[idx];
        uint32_t h01, l01, h23, l23;
        split2(v.x, v.y, h01, l01);
        split2(v.z, v.w, h23, l23);
        reinterpret_cast<uint2*>(g_xhi)[idx] = make_uint2(h01, h23);
        reinterpret_cast<uint2*>(g_xlo)[idx] = make_uint2(l01, l23);
        return;
    }

    if (blockIdx.x >= 2144) {
        // zero out's O region (4,194,304 floats = 1,048,576 float4)
        int bz = blockIdx.x - 2144;
        int idx = bz * 256 + t;
        reinterpret_cast<float4*>(out_zero)[idx] =
            make_float4(0.f, 0.f, 0.f, 0.f);
        if (bz == 0) {            // also zero the per-tile Z counters
            g_zctr[t] = 0;
            g_zctr[t + 256] = 0;
        }
        return;
    }

    const int bw = blockIdx.x - 2048;       // 0..95
    const int f0 = (bw & 3) * 64;
    const int h  = (bw >> 2) & 7;
    const int z  = bw >> 5;
    const float* W = (z == 0) ? Wq : (z == 1) ? Wk : Wv;

    const int r    = t >> 2;
    const int quad = t & 3;
#pragma unroll
    for (int j = 0; j < 4; j++) {
        int e = quad * 16 + j * 4;
        float4 v = *reinterpret_cast<const float4*>(
            &W[(size_t)(h * Fv + f0 + r) * Ev + e]);
        ws[r][e + 0] = v.x; ws[r][e + 1] = v.y;
        ws[r][e + 2] = v.z; ws[r][e + 3] = v.w;
    }
    __syncthreads();

    __nv_bfloat16* whi = g_wthi + ((size_t)(z * Hv + h) * Ev + r) * Fv + f0;
    __nv_bfloat16* wlo = g_wtlo + ((size_t)(z * Hv + h) * Ev + r) * Fv + f0;
#pragma unroll
    for (int j = 0; j < 4; j++) {
        int f = quad * 16 + j * 4;
        float v0 = ws[f + 0][r], v1 = ws[f + 1][r];
        float v2 = ws[f + 2][r], v3 = ws[f + 3][r];
        uint32_t h01, l01, h23, l23;
        split2(v0, v1, h01, l01);
        split2(v2, v3, h23, l23);
        *reinterpret_cast<uint2*>(whi + f) = make_uint2(h01, h23);
        *reinterpret_cast<uint2*>(wlo + f) = make_uint2(l01, l23);
    }
}

// ---------------------------------------------------------------------------
// Kernel 1: tensor-core projection (3-term split-bf16), grid-launched,
// 2 CTAs/SM. V staged via smem, coalesced STG.  (unchanged from R15)
// ---------------------------------------------------------------------------
#define PB_WLO 9216
#define PB_XHI 18432
#define PB_XLO 36864
#define PB_SZ  55296
#define PROJ_SMEM (2 * PB_SZ)

__device__ __forceinline__ void proj_prefetch(
    uint32_t buf, const __nv_bfloat16* whi_g, const __nv_bfloat16* wlo_g,
    int row0, int c, int t)
{
#pragma unroll
    for (int i = 0; i < 2; i++) {
        int idx = t + 256 * i;
        int row = idx >> 3, u = idx & 7;
        cp16(buf + row * 144 + u * 16,
             whi_g + (size_t)row * 256 + c * 64 + u * 8);
        cp16(buf + PB_WLO + row * 144 + u * 16,
             wlo_g + (size_t)row * 256 + c * 64 + u * 8);
    }
#pragma unroll
    for (int i = 0; i < 4; i++) {
        int idx = t + 256 * i;
        int row = idx >> 3, u = idx & 7;
        cp16(buf + PB_XHI + row * 144 + u * 16,
             g_xhi + (size_t)(row0 + row) * 256 + c * 64 + u * 8);
        cp16(buf + PB_XLO + row * 144 + u * 16,
             g_xlo + (size_t)(row0 + row) * 256 + c * 64 + u * 8);
    }
}

__global__ __launch_bounds__(256, 2) void proj_mma_kernel()
{
    extern __shared__ char smem[];
    const uint32_t sb = smem_to_u32(smem);
    const int t    = threadIdx.x;
    const int w    = t >> 5;
    const int lane = t & 31;
    const int g    = lane >> 2;
    const int tq   = lane & 3;

    const int rb = blockIdx.x;
    const int h  = blockIdx.y;
    const int z  = blockIdx.z;
    const int row0 = rb * 128;

    const __nv_bfloat16* whi_g = g_wthi + (size_t)(z * Hv + h) * Ev * Fv;
    const __nv_bfloat16* wlo_g = g_wtlo + (size_t)(z * Hv + h) * Ev * Fv;

    proj_prefetch(sb, whi_g, wlo_g, row0, 0, t);
    CP_COMMIT();

    float acc[8][4];
#pragma unroll
    for (int et = 0; et < 8; et++)
#pragma unroll
        for (int q = 0; q < 4; q++) acc[et][q] = 0.f;

    const uint32_t abase = (uint32_t)((w * 16 + (lane & 15)) * 144 +
                                      (lane >> 4) * 16);
    const uint32_t brow  = (uint32_t)((lane & 7) * 144 + (lane >> 3) * 16);

    for (int c = 0; c < 4; c++) {
        if (c < 3) {
            proj_prefetch(sb + ((c + 1) & 1) * PB_SZ, whi_g, wlo_g,
                          row0, c + 1, t);
            CP_COMMIT();
            CP_WAIT1();
        } else {
            CP_WAIT0();
        }
        __syncthreads();

        const uint32_t xb = sb + (c & 1) * PB_SZ;

        uint32_t ah[4][4], al[4][4];
#pragma unroll
        for (int ks = 0; ks < 4; ks++) {
            ldsm4(ah[ks], xb + PB_XHI + abase + ks * 32);
            ldsm4(al[ks], xb + PB_XLO + abase + ks * 32);
        }

#pragma unroll
        for (int et = 0; et < 8; et++) {
            uint32_t bt = xb + (uint32_t)(et * 1152) + brow;
            uint32_t bh[8], bl[8];
            ldsm4(bh,     bt);
            ldsm4(bh + 4, bt + 64);
            ldsm4(bl,     bt + PB_WLO);
            ldsm4(bl + 4, bt + PB_WLO + 64);
#pragma unroll
            for (int ks = 0; ks < 4; ks++) {
                mma_bf16(acc[et], ah[ks], bh + 2 * ks);
                mma_bf16(acc[et], al[ks], bh + 2 * ks);
                mma_bf16(acc[et], ah[ks], bl + 2 * ks);
            }
        }
        __syncthreads();
    }

    const int rloc = w * 16 + g;
    const int r0   = row0 + rloc;
    if (z != 2) {
        __half* dsthi = (z == 0) ? g_qhi : g_khi;
        __half* dstlo = (z == 0) ? g_qlo : g_klo;
        size_t baseA = ((size_t)h * 8192 + r0) * 64;
        size_t baseB = ((size_t)h * 8192 + r0 + 8) * 64;
#pragma unroll
        for (int et = 0; et < 8; et++) {
            int e = et * 8 + 2 * tq;
            uint32_t hA, lA, hB, lB;
            split2h(acc[et][0], acc[et][1], hA, lA);
            split2h(acc[et][2], acc[et][3], hB, lB);
            *reinterpret_cast<uint32_t*>(dsthi + baseA + e) = hA;
            *reinterpret_cast<uint32_t*>(dstlo + baseA + e) = lA;
            *reinterpret_cast<uint32_t*>(dsthi + baseB + e) = hB;
            *reinterpret_cast<uint32_t*>(dstlo + baseB + e) = lB;
        }
    } else {
        __half* vt = reinterpret_cast<__half*>(smem);
#pragma unroll
        for (int et = 0; et < 8; et++) {
            int e0 = et * 8 + 2 * tq;
            vt[(e0 + 0) * 136 + rloc]     = __float2half(acc[et][0]);
            vt[(e0 + 1) * 136 + rloc]     = __float2half(acc[et][1]);
            vt[(e0 + 0) * 136 + rloc + 8] = __float2half(acc[et][2]);
            vt[(e0 + 1) * 136 + rloc + 8] = __float2half(acc[et][3]);
        }
        __syncthreads();

        const int bA = rb >> 3;
        const int n0 = (rb & 7) * 128;
        __half* vbase = g_vthi + (size_t)(h * 8 + bA) * 64 * 1024;
#pragma unroll
        for (int i = 0; i < 4; i++) {
            int idx = t + 256 * i;
            int e = idx >> 4, u = idx & 15;
            uint4 v = *reinterpret_cast<const uint4*>(vt + e * 136 + u * 8);
            *reinterpret_cast<uint4*>(vbase + (size_t)e * 1024 + n0 + u * 8) = v;
        }
    }
}

// ---------------------------------------------------------------------------
// Kernel 2: two-pass attention, KEY-QUARTERED subtiles (2048 units).
// Subtile = 128 q-rows x 256 keys. Z combined across 4 subtiles via global
// zpart + counter; O combined via RED.ADD into pre-zeroed out.
// ---------------------------------------------------------------------------
#define ABUF_SZ  36864
#define A_KLO128 18432
#define B_KLO    9216
#define B_VHI    18432
#define ATTN_SMEM (2 * ABUF_SZ)
#define NSUB  2048

__device__ __forceinline__ void prefetchK128(
    uint32_t buf, const __half* khi, const __half* klo, int m0, int t)
{
#pragma unroll
    for (int i = 0; i < 4; i++) {
        int idx = t + 256 * i;
        int row = idx >> 3, u = idx & 7;
        cp16(buf + row * 144 + u * 16, khi + (size_t)(m0 + row) * 64 + u * 8);
        cp16(buf + A_KLO128 + row * 144 + u * 16,
             klo + (size_t)(m0 + row) * 64 + u * 8);
    }
}

__device__ __forceinline__ void prefetchKV64(
    uint32_t buf,
    const __half* khi, const __half* klo, const __half* vhi,
    int m0, int t)
{
#pragma unroll
    for (int i = 0; i < 2; i++) {
        int idx = t + 256 * i;
        int row = idx >> 3, u = idx & 7;
        cp16(buf + row * 144 + u * 16, khi + (size_t)(m0 + row) * 64 + u * 8);
        cp16(buf + B_KLO + row * 144 + u * 16,
             klo + (size_t)(m0 + row) * 64 + u * 8);
        cp16(buf + B_VHI + row * 144 + u * 16,
             vhi + (size_t)row * 1024 + m0 + u * 8);
    }
}

__global__ __launch_bounds__(256, 2) void attn_mma_kernel(
    float* __restrict__ attn, float* __restrict__ out)
{
    extern __shared__ char smem[];
    __shared__ unsigned int s_tile;
    const uint32_t sb = smem_to_u32(smem);
    const int t    = threadIdx.x;
    const int w    = t >> 5;
    const int lane = t & 31;
    const int g    = lane >> 2;
    const int tq   = lane & 3;

    const uint32_t rowoff = (uint32_t)((lane & 7) * 144 + (lane >> 3) * 16);

    for (;;) {
        if (t == 0) s_tile = atomicAdd(&g_tile_ctr, 1u);
        __syncthreads();
        const unsigned int sub = s_tile;
        if (sub >= NSUB) break;

        const int tile = (int)(sub >> 2);
        const int qs   = (int)(sub & 3);
        const int hb   = tile >> 3;
        const int qblk = tile & 7;
        const int h    = hb >> 3;
        const int b    = hb & 7;
        const int row0 = qblk * 128;
        const int kb0  = qs * 256;          // key base for this subtile

        const __half* qhi = g_qhi + ((size_t)hb * 1024 + row0) * 64;
        const __half* qlo = g_qlo + ((size_t)hb * 1024 + row0) * 64;
        const __half* khi = g_khi + (size_t)hb * 1024 * 64;
        const __half* klo = g_klo + (size_t)hb * 1024 * 64;
        const __half* vhi = g_vthi + (size_t)hb * 64 * 1024;

        prefetchK128(sb, khi, klo, kb0, t);
        CP_COMMIT();
        prefetchK128(sb + ABUF_SZ, khi, klo, kb0 + 128, t);
        CP_COMMIT();

        // ---- Q fragments via LDG (L2-resident) ----
        const int rlA = w * 16 + g;
        uint32_t qh[4][4], ql[4][4];
#pragma unroll
        for (int kk = 0; kk < 4; kk++) {
            int e0 = kk * 16 + 2 * tq;
            qh[kk][0] = *reinterpret_cast<const uint32_t*>(qhi + (size_t)rlA * 64 + e0);
            qh[kk][1] = *reinterpret_cast<const uint32_t*>(qhi + (size_t)(rlA + 8) * 64 + e0);
            qh[kk][2] = *reinterpret_cast<const uint32_t*>(qhi + (size_t)rlA * 64 + e0 + 8);
            qh[kk][3] = *reinterpret_cast<const uint32_t*>(qhi + (size_t)(rlA + 8) * 64 + e0 + 8);
            ql[kk][0] = *reinterpret_cast<const uint32_t*>(qlo + (size_t)rlA * 64 + e0);
            ql[kk][1] = *reinterpret_cast<const uint32_t*>(qlo + (size_t)(rlA + 8) * 64 + e0);
            ql[kk][2] = *reinterpret_cast<const uint32_t*>(qlo + (size_t)rlA * 64 + e0 + 8);
            ql[kk][3] = *reinterpret_cast<const uint32_t*>(qlo + (size_t)(rlA + 8) * 64 + e0 + 8);
        }

        float z0 = 0.f, z1 = 0.f;

        // ===== pass A: partial Z over 256 keys (2 x 128-key chunks) =======
        for (int ch = 0; ch < 2; ch++) {
            CP_WAIT1();
            __syncthreads();
            const uint32_t kb = sb + ch * ABUF_SZ;
#pragma unroll
            for (int nt = 0; nt < 16; nt++) {
                uint32_t addr = kb + (uint32_t)(nt * 8 * 144) + rowoff;
                uint32_t bh[8], bl[8];
                ldsm4(bh,     addr);
                ldsm4(bh + 4, addr + 64);
                ldsm4(bl,     addr + A_KLO128);
                ldsm4(bl + 4, addr + A_KLO128 + 64);
                float acc[4] = {0.f, 0.f, 0.f, 0.f};
#pragma unroll
                for (int kk = 0; kk < 4; kk++) {
                    mma_f16(acc, qh[kk], bh + 2 * kk);
                    mma_f16(acc, ql[kk], bh + 2 * kk);
                    mma_f16(acc, qh[kk], bl + 2 * kk);
                }
                z0 += __expf(acc[0]) + __expf(acc[1]);
                z1 += __expf(acc[2]) + __expf(acc[3]);
            }
            __syncthreads();
            // reuse this buffer for pass-B chunk ch (keys kb0 + ch*64)
            prefetchKV64(kb, khi, klo, vhi, kb0 + ch * 64, t);
            CP_COMMIT();
        }

        // ===== publish partial Z, combine across subtiles =================
        z0 += __shfl_xor_sync(0xffffffffu, z0, 1);
        z0 += __shfl_xor_sync(0xffffffffu, z0, 2);
        z1 += __shfl_xor_sync(0xffffffffu, z1, 1);
        z1 += __shfl_xor_sync(0xffffffffu, z1, 2);
        if (tq == 0) {
            g_zpart[(size_t)sub * 128 + rlA]     = z0;
            g_zpart[(size_t)sub * 128 + rlA + 8] = z1;
        }
        __threadfence();
        __syncthreads();
        if (t == 0) {
            atomicAdd(&g_zctr[tile], 1);
            while (atomicAdd(&g_zctr[tile], 0) < 4) { }
        }
        __syncthreads();
        __threadfence();

        float zf0 = z0, zf1 = z1;
#pragma unroll
        for (int s = 0; s < 4; s++) {
            if (s != qs) {
                zf0 += g_zpart[(size_t)(tile * 4 + s) * 128 + rlA];
                zf1 += g_zpart[(size_t)(tile * 4 + s) * 128 + rlA + 8];
            }
        }
        const float iz0 = 1.f / zf0;
        const float iz1 = 1.f / zf1;

        // ===== pass B: attn store + AV over this quarter (4 x 64 keys) ====
        float oacc[8][4];
#pragma unroll
        for (int nt = 0; nt < 8; nt++)
#pragma unroll
            for (int q = 0; q < 4; q++) oacc[nt][q] = 0.f;

        float* aA = attn ? attn + ((size_t)(hb * 1024 + row0 + rlA)) * 1024 +
                           kb0 + 2 * tq
                         : nullptr;
        float* aB = attn ? aA + 8 * 1024 : nullptr;

        for (int ch = 0; ch < 4; ch++) {
            if (ch < 3) { CP_WAIT1(); } else { CP_WAIT0(); }
            __syncthreads();

            const uint32_t kb = sb + (ch & 1) * ABUF_SZ;

#pragma unroll
            for (int grp = 0; grp < 2; grp++) {
                uint32_t ph[2][4];
#pragma unroll
                for (int nt4 = 0; nt4 < 4; nt4++) {
                    int gnt = grp * 4 + nt4;
                    uint32_t addr = kb + (uint32_t)(gnt * 8 * 144) + rowoff;
                    uint32_t bh[8], bl[8];
                    ldsm4(bh,     addr);
                    ldsm4(bh + 4, addr + 64);
                    ldsm4(bl,     addr + B_KLO);
                    ldsm4(bl + 4, addr + B_KLO + 64);
                    float acc[4] = {0.f, 0.f, 0.f, 0.f};
#pragma unroll
                    for (int kk = 0; kk < 4; kk++) {
                        mma_f16(acc, qh[kk], bh + 2 * kk);
                        mma_f16(acc, ql[kk], bh + 2 * kk);
                        mma_f16(acc, qh[kk], bl + 2 * kk);
                    }
                    float e0 = __expf(acc[0]) * iz0;
                    float e1 = __expf(acc[1]) * iz0;
                    float e2 = __expf(acc[2]) * iz1;
                    float e3 = __expf(acc[3]) * iz1;
                    if (aA) {
                        *reinterpret_cast<float2*>(aA + ch * 64 + gnt * 8) =
                            make_float2(e0, e1);
                        *reinterpret_cast<float2*>(aB + ch * 64 + gnt * 8) =
                            make_float2(e2, e3);
                    }
                    int jtl = nt4 >> 1, off = (nt4 & 1) * 2;
                    ph[jtl][off + 0] = pack2h(e0, e1);
                    ph[jtl][off + 1] = pack2h(e2, e3);
                }

#pragma unroll
                for (int nt = 0; nt < 8; nt++) {
                    uint32_t va = kb + B_VHI + (uint32_t)(nt * 8 * 144) +
                                  rowoff + grp * 64;
                    uint32_t vh4[4];
                    ldsm4(vh4, va);
#pragma unroll
                    for (int j = 0; j < 2; j++) {
                        mma_f16(oacc[nt], ph[j], vh4 + 2 * j);
                    }
                }
            }
            __syncthreads();
            if (ch < 2) {
                // refill this buffer with chunk ch+2 (keys kb0 + (ch+2)*64)
                prefetchKV64(kb, khi, klo, vhi, kb0 + (ch + 2) * 64, t);
                CP_COMMIT();
            }
        }

        // ===== combine O: RED.ADD into pre-zeroed out ======================
        float* oA = out + ((size_t)b * 1024 + row0 + rlA) * 512 + h * 64 + 2 * tq;
        float* oB = oA + 8 * 512;
#pragma unroll
        for (int nt = 0; nt < 8; nt++) {
            atomicAdd(&oA[8 * nt],     oacc[nt][0] * SCALING);
            atomicAdd(&oA[8 * nt + 1], oacc[nt][1] * SCALING);
            atomicAdd(&oB[8 * nt],     oacc[nt][2] * SCALING);
            atomicAdd(&oB[8 * nt + 1], oacc[nt][3] * SCALING);
        }
        __syncthreads();
    }
}

// ---------------------------------------------------------------------------
extern "C" void kernel_launch(void* const* d_in, const int* in_sizes, int n_in,
                              void* d_out, int out_size)
{
    const float* x  = (const float*)d_in[0];
    const float* Wq = (const float*)d_in[1];
    const float* Wk = (const float*)d_in[2];
    const float* Wv = (const float*)d_in[3];

    const size_t attn_elems = (size_t)Hv * Bv * Nv * Nv;
    float* attn = (float*)d_out;
    float* out  = (float*)d_out + attn_elems;
    if ((size_t)out_size < attn_elems + (size_t)Bv * Nv * Hv * Ev) {
        attn = nullptr;
        out  = (float*)d_out;
    }

    cudaFuncSetAttribute(proj_mma_kernel,
                         cudaFuncAttributeMaxDynamicSharedMemorySize, PROJ_SMEM);
    cudaFuncSetAttribute(attn_mma_kernel,
                         cudaFuncAttributeMaxDynamicSharedMemorySize, ATTN_SMEM);

    split_inputs_kernel<<<6240, 256>>>(x, Wq, Wk, Wv, out);  // + zero O, reset ctrs
    proj_mma_kernel<<<dim3(64, 8, 3), 256, PROJ_SMEM>>>();
    attn_mma_kernel<<<296, 256, ATTN_SMEM>>>(attn, out);
}

// round 17
// speedup vs baseline: 1.1213x; 1.1213x over previous
#include <cuda_runtime.h>
#include <cuda_bf16.h>
#include <cuda_fp16.h>
#include <math.h>
#include <stdint.h>

#define Bv 8
#define Nv 1024
#define Fv 256
#define Hv 8
#define Ev 64
#define SCALING 0.125f

// ---------------- operand buffers (static scratch) ----------------
// fp16 splits for attention (V: hi only)
__device__ __half g_qhi[Hv * Bv * Nv * Ev];
__device__ __half g_qlo[Hv * Bv * Nv * Ev];
__device__ __half g_khi[Hv * Bv * Nv * Ev];
__device__ __half g_klo[Hv * Bv * Nv * Ev];
__device__ __half g_vthi[Hv * Bv * Ev * Nv];          // [hb][e][n] transposed

// fp16 splits for tensor-core projection
__device__ __half g_xhi[Bv * Nv * Fv];
__device__ __half g_xlo[Bv * Nv * Fv];
__device__ __half g_wthi[3 * Hv * Ev * Fv];           // [z][h][e][f]
__device__ __half g_wtlo[3 * Hv * Ev * Fv];

// work queue (attn)
__device__ unsigned int g_tile_ctr;

// ---------------- helpers ----------------
__device__ __forceinline__ uint32_t smem_to_u32(const void* p) {
    uint32_t a;
    asm("{ .reg .u64 tmp; cvta.to.shared.u64 tmp, %1; cvt.u32.u64 %0, tmp; }"
        : "=r"(a) : "l"(p));
    return a;
}

__device__ __forceinline__ void cp16(uint32_t dst, const void* src) {
    asm volatile("cp.async.cg.shared.global [%0], [%1], 16;"
                 :: "r"(dst), "l"(src));
}
#define CP_COMMIT() asm volatile("cp.async.commit_group;")
#define CP_WAIT1()  asm volatile("cp.async.wait_group 1;")
#define CP_WAIT0()  asm volatile("cp.async.wait_group 0;")

__device__ __forceinline__ void ldsm4(uint32_t* r, uint32_t addr) {
    asm volatile("ldmatrix.sync.aligned.m8n8.x4.shared.b16 {%0,%1,%2,%3}, [%4];"
                 : "=r"(r[0]), "=r"(r[1]), "=r"(r[2]), "=r"(r[3]) : "r"(addr));
}

__device__ __forceinline__ void mma_f16(float* d, const uint32_t* a, const uint32_t* b) {
    asm volatile(
        "mma.sync.aligned.m16n8k16.row.col.f32.f16.f16.f32 "
        "{%0,%1,%2,%3}, {%4,%5,%6,%7}, {%8,%9}, {%0,%1,%2,%3};"
        : "+f"(d[0]), "+f"(d[1]), "+f"(d[2]), "+f"(d[3])
        : "r"(a[0]), "r"(a[1]), "r"(a[2]), "r"(a[3]), "r"(b[0]), "r"(b[1]));
}

// fp16 split
__device__ __forceinline__ void split2h(float a, float b, uint32_t& hi, uint32_t& lo) {
    __half2 h2 = __floats2half2_rn(a, b);
    float2 hf = __half22float2(h2);
    __half2 l2 = __floats2half2_rn(a - hf.x, b - hf.y);
    hi = *reinterpret_cast<uint32_t*>(&h2);
    lo = *reinterpret_cast<uint32_t*>(&l2);
}

// fp16 pack (no split)
__device__ __forceinline__ uint32_t pack2h(float a, float b) {
    __half2 h2 = __floats2half2_rn(a, b);
    return *reinterpret_cast<uint32_t*>(&h2);
}

// ---------------------------------------------------------------------------
// Kernel 0: merged input splits (x -> fp16 hi/lo ; W -> transposed fp16 hi/lo)
// Also resets the attn work queue.
// ---------------------------------------------------------------------------
__global__ __launch_bounds__(256) void split_inputs_kernel(
    const float* __restrict__ x,
    const float* __restrict__ Wq, const float* __restrict__ Wk,
    const float* __restrict__ Wv)
{
    __shared__ float ws[64][65];
    const int t = threadIdx.x;
    if (blockIdx.x == 0 && t == 0) g_tile_ctr = 0;

    if (blockIdx.x < 2048) {
        int idx = blockIdx.x * 256 + t;
        float4 v = reinterpret_cast<const float4*>(x)[idx];
        uint32_t h01, l01, h23, l23;
        split2h(v.x, v.y, h01, l01);
        split2h(v.z, v.w, h23, l23);
        reinterpret_cast<uint2*>(g_xhi)[idx] = make_uint2(h01, h23);
        reinterpret_cast<uint2*>(g_xlo)[idx] = make_uint2(l01, l23);
        return;
    }

    const int bw = blockIdx.x - 2048;       // 0..95
    const int f0 = (bw & 3) * 64;
    const int h  = (bw >> 2) & 7;
    const int z  = bw >> 5;
    const float* W = (z == 0) ? Wq : (z == 1) ? Wk : Wv;

    const int r    = t >> 2;
    const int quad = t & 3;
#pragma unroll
    for (int j = 0; j < 4; j++) {
        int e = quad * 16 + j * 4;
        float4 v = *reinterpret_cast<const float4*>(
            &W[(size_t)(h * Fv + f0 + r) * Ev + e]);
        ws[r][e + 0] = v.x; ws[r][e + 1] = v.y;
        ws[r][e + 2] = v.z; ws[r][e + 3] = v.w;
    }
    __syncthreads();

    __half* whi = g_wthi + ((size_t)(z * Hv + h) * Ev + r) * Fv + f0;
    __half* wlo = g_wtlo + ((size_t)(z * Hv + h) * Ev + r) * Fv + f0;
#pragma unroll
    for (int j = 0; j < 4; j++) {
        int f = quad * 16 + j * 4;
        float v0 = ws[f + 0][r], v1 = ws[f + 1][r];
        float v2 = ws[f + 2][r], v3 = ws[f + 3][r];
        uint32_t h01, l01, h23, l23;
        split2h(v0, v1, h01, l01);
        split2h(v2, v3, h23, l23);
        *reinterpret_cast<uint2*>(whi + f) = make_uint2(h01, h23);
        *reinterpret_cast<uint2*>(wlo + f) = make_uint2(l01, l23);
    }
}

// ---------------------------------------------------------------------------
// Kernel 1: tensor-core projection, fp16 splits, grid-launched, 2 CTAs/SM.
// q/k: 3-term. V: 1-term (hi x hi) -- lo planes neither loaded nor read.
// Epilogue: q/k fp16 splits; V staged via smem, coalesced STG.
// ---------------------------------------------------------------------------
#define PB_WLO 9216
#define PB_XHI 18432
#define PB_XLO 36864
#define PB_SZ  55296
#define PROJ_SMEM (2 * PB_SZ)           // 110592

__device__ __forceinline__ void proj_prefetch(
    uint32_t buf, const __half* whi_g, const __half* wlo_g,
    int row0, int c, int t, bool loadLo)
{
#pragma unroll
    for (int i = 0; i < 2; i++) {
        int idx = t + 256 * i;
        int row = idx >> 3, u = idx & 7;
        cp16(buf + row * 144 + u * 16,
             whi_g + (size_t)row * 256 + c * 64 + u * 8);
        if (loadLo)
            cp16(buf + PB_WLO + row * 144 + u * 16,
                 wlo_g + (size_t)row * 256 + c * 64 + u * 8);
    }
#pragma unroll
    for (int i = 0; i < 4; i++) {
        int idx = t + 256 * i;
        int row = idx >> 3, u = idx & 7;
        cp16(buf + PB_XHI + row * 144 + u * 16,
             g_xhi + (size_t)(row0 + row) * 256 + c * 64 + u * 8);
        if (loadLo)
            cp16(buf + PB_XLO + row * 144 + u * 16,
                 g_xlo + (size_t)(row0 + row) * 256 + c * 64 + u * 8);
    }
}

__global__ __launch_bounds__(256, 2) void proj_mma_kernel()
{
    extern __shared__ char smem[];
    const uint32_t sb = smem_to_u32(smem);
    const int t    = threadIdx.x;
    const int w    = t >> 5;
    const int lane = t & 31;
    const int g    = lane >> 2;
    const int tq   = lane & 3;

    const int rb = blockIdx.x;
    const int h  = blockIdx.y;
    const int z  = blockIdx.z;
    const int row0 = rb * 128;
    const bool threeTerm = (z != 2);

    const __half* whi_g = g_wthi + (size_t)(z * Hv + h) * Ev * Fv;
    const __half* wlo_g = g_wtlo + (size_t)(z * Hv + h) * Ev * Fv;

    proj_prefetch(sb, whi_g, wlo_g, row0, 0, t, threeTerm);
    CP_COMMIT();

    float acc[8][4];
#pragma unroll
    for (int et = 0; et < 8; et++)
#pragma unroll
        for (int q = 0; q < 4; q++) acc[et][q] = 0.f;

    const uint32_t abase = (uint32_t)((w * 16 + (lane & 15)) * 144 +
                                      (lane >> 4) * 16);
    const uint32_t brow  = (uint32_t)((lane & 7) * 144 + (lane >> 3) * 16);

    for (int c = 0; c < 4; c++) {
        if (c < 3) {
            proj_prefetch(sb + ((c + 1) & 1) * PB_SZ, whi_g, wlo_g,
                          row0, c + 1, t, threeTerm);
            CP_COMMIT();
            CP_WAIT1();
        } else {
            CP_WAIT0();
        }
        __syncthreads();

        const uint32_t xb = sb + (c & 1) * PB_SZ;

        uint32_t ah[4][4], al[4][4];
#pragma unroll
        for (int ks = 0; ks < 4; ks++) {
            ldsm4(ah[ks], xb + PB_XHI + abase + ks * 32);
            if (threeTerm) ldsm4(al[ks], xb + PB_XLO + abase + ks * 32);
        }

#pragma unroll
        for (int et = 0; et < 8; et++) {
            uint32_t bt = xb + (uint32_t)(et * 1152) + brow;
            uint32_t bh[8], bl[8];
            ldsm4(bh,     bt);
            ldsm4(bh + 4, bt + 64);
            if (threeTerm) {
                ldsm4(bl,     bt + PB_WLO);
                ldsm4(bl + 4, bt + PB_WLO + 64);
            }
#pragma unroll
            for (int ks = 0; ks < 4; ks++) {
                mma_f16(acc[et], ah[ks], bh + 2 * ks);
                if (threeTerm) {
                    mma_f16(acc[et], al[ks], bh + 2 * ks);
                    mma_f16(acc[et], ah[ks], bl + 2 * ks);
                }
            }
        }
        __syncthreads();
    }

    const int rloc = w * 16 + g;
    const int r0   = row0 + rloc;
    if (z != 2) {
        __half* dsthi = (z == 0) ? g_qhi : g_khi;
        __half* dstlo = (z == 0) ? g_qlo : g_klo;
        size_t baseA = ((size_t)h * 8192 + r0) * 64;
        size_t baseB = ((size_t)h * 8192 + r0 + 8) * 64;
#pragma unroll
        for (int et = 0; et < 8; et++) {
            int e = et * 8 + 2 * tq;
            uint32_t hA, lA, hB, lB;
            split2h(acc[et][0], acc[et][1], hA, lA);
            split2h(acc[et][2], acc[et][3], hB, lB);
            *reinterpret_cast<uint32_t*>(dsthi + baseA + e) = hA;
            *reinterpret_cast<uint32_t*>(dstlo + baseA + e) = lA;
            *reinterpret_cast<uint32_t*>(dsthi + baseB + e) = hB;
            *reinterpret_cast<uint32_t*>(dstlo + baseB + e) = lB;
        }
    } else {
        // ---- V: stage transposed tile in smem, then coalesced STG ----
        __half* vt = reinterpret_cast<__half*>(smem);   // reuse buffer 0
#pragma unroll
        for (int et = 0; et < 8; et++) {
            int e0 = et * 8 + 2 * tq;
            vt[(e0 + 0) * 136 + rloc]     = __float2half(acc[et][0]);
            vt[(e0 + 1) * 136 + rloc]     = __float2half(acc[et][1]);
            vt[(e0 + 0) * 136 + rloc + 8] = __float2half(acc[et][2]);
            vt[(e0 + 1) * 136 + rloc + 8] = __float2half(acc[et][3]);
        }
        __syncthreads();

        const int bA = rb >> 3;
        const int n0 = (rb & 7) * 128;
        __half* vbase = g_vthi + (size_t)(h * 8 + bA) * 64 * 1024;
#pragma unroll
        for (int i = 0; i < 4; i++) {
            int idx = t + 256 * i;            // 0..1023
            int e = idx >> 4, u = idx & 15;
            uint4 v = *reinterpret_cast<const uint4*>(vt + e * 136 + u * 8);
            *reinterpret_cast<uint4*>(vbase + (size_t)e * 1024 + n0 + u * 8) = v;
        }
    }
}

// ---------------------------------------------------------------------------
// Kernel 2: two-pass mma attention (R13/R15, frozen / best known).
// Pass A: 128-key K-only chunks (x8). Pass B: 64-key K hi/lo + V hi (x16).
// AV = single-term P(hi) x V(hi). smem 73728 -> 2 CTAs/SM.
// ---------------------------------------------------------------------------
#define ABUF_SZ  36864
#define A_KLO128 18432
#define B_KLO    9216
#define B_VHI    18432
#define ATTN_SMEM (2 * ABUF_SZ)        // 73728
#define NTILES  512

__device__ __forceinline__ void prefetchK128(
    uint32_t buf, const __half* khi, const __half* klo, int m0, int t)
{
#pragma unroll
    for (int i = 0; i < 4; i++) {
        int idx = t + 256 * i;
        int row = idx >> 3, u = idx & 7;
        cp16(buf + row * 144 + u * 16, khi + (size_t)(m0 + row) * 64 + u * 8);
        cp16(buf + A_KLO128 + row * 144 + u * 16,
             klo + (size_t)(m0 + row) * 64 + u * 8);
    }
}

__device__ __forceinline__ void prefetchKV64(
    uint32_t buf,
    const __half* khi, const __half* klo, const __half* vhi,
    int m0, int t)
{
#pragma unroll
    for (int i = 0; i < 2; i++) {
        int idx = t + 256 * i;
        int row = idx >> 3, u = idx & 7;
        cp16(buf + row * 144 + u * 16, khi + (size_t)(m0 + row) * 64 + u * 8);
        cp16(buf + B_KLO + row * 144 + u * 16,
             klo + (size_t)(m0 + row) * 64 + u * 8);
        cp16(buf + B_VHI + row * 144 + u * 16,
             vhi + (size_t)row * 1024 + m0 + u * 8);
    }
}

__global__ __launch_bounds__(256, 2) void attn_mma_kernel(
    float* __restrict__ attn, float* __restrict__ out)
{
    extern __shared__ char smem[];
    __shared__ unsigned int s_tile;
    const uint32_t sb = smem_to_u32(smem);
    const int t    = threadIdx.x;
    const int w    = t >> 5;
    const int lane = t & 31;
    const int g    = lane >> 2;
    const int tq   = lane & 3;

    const uint32_t rowoff = (uint32_t)((lane & 7) * 144 + (lane >> 3) * 16);

    for (;;) {
        if (t == 0) s_tile = atomicAdd(&g_tile_ctr, 1u);
        __syncthreads();
        const unsigned int tile = s_tile;
        if (tile >= NTILES) break;

        const int hb   = (int)(tile >> 3);
        const int qblk = (int)(tile & 7);
        const int h    = hb >> 3;
        const int b    = hb & 7;
        const int row0 = qblk * 128;

        const __half* qhi = g_qhi + ((size_t)hb * 1024 + row0) * 64;
        const __half* qlo = g_qlo + ((size_t)hb * 1024 + row0) * 64;
        const __half* khi = g_khi + (size_t)hb * 1024 * 64;
        const __half* klo = g_klo + (size_t)hb * 1024 * 64;
        const __half* vhi = g_vthi + (size_t)hb * 64 * 1024;

        prefetchK128(sb, khi, klo, 0, t);
        CP_COMMIT();

        // ---- Q fragments via LDG (L2-resident) ----
        const int rlA = w * 16 + g;
        uint32_t qh[4][4], ql[4][4];
#pragma unroll
        for (int kk = 0; kk < 4; kk++) {
            int e0 = kk * 16 + 2 * tq;
            qh[kk][0] = *reinterpret_cast<const uint32_t*>(qhi + (size_t)rlA * 64 + e0);
            qh[kk][1] = *reinterpret_cast<const uint32_t*>(qhi + (size_t)(rlA + 8) * 64 + e0);
            qh[kk][2] = *reinterpret_cast<const uint32_t*>(qhi + (size_t)rlA * 64 + e0 + 8);
            qh[kk][3] = *reinterpret_cast<const uint32_t*>(qhi + (size_t)(rlA + 8) * 64 + e0 + 8);
            ql[kk][0] = *reinterpret_cast<const uint32_t*>(qlo + (size_t)rlA * 64 + e0);
            ql[kk][1] = *reinterpret_cast<const uint32_t*>(qlo + (size_t)(rlA + 8) * 64 + e0);
            ql[kk][2] = *reinterpret_cast<const uint32_t*>(qlo + (size_t)rlA * 64 + e0 + 8);
            ql[kk][3] = *reinterpret_cast<const uint32_t*>(qlo + (size_t)(rlA + 8) * 64 + e0 + 8);
        }

        float z0 = 0.f, z1 = 0.f;

        // ================= pass A: Z = sum exp(s), 128-key chunks =========
        for (int ch = 0; ch < 8; ch++) {
            if (ch < 7) {
                prefetchK128(sb + ((ch + 1) & 1) * ABUF_SZ, khi, klo,
                             (ch + 1) * 128, t);
                CP_COMMIT();
                CP_WAIT1();
            } else {
                CP_WAIT0();
            }
            __syncthreads();

            const uint32_t kb = sb + (ch & 1) * ABUF_SZ;
#pragma unroll
            for (int nt = 0; nt < 16; nt++) {
                uint32_t addr = kb + (uint32_t)(nt * 8 * 144) + rowoff;
                uint32_t bh[8], bl[8];
                ldsm4(bh,     addr);
                ldsm4(bh + 4, addr + 64);
                ldsm4(bl,     addr + A_KLO128);
                ldsm4(bl + 4, addr + A_KLO128 + 64);
                float acc[4] = {0.f, 0.f, 0.f, 0.f};
#pragma unroll
                for (int kk = 0; kk < 4; kk++) {
                    mma_f16(acc, qh[kk], bh + 2 * kk);
                    mma_f16(acc, ql[kk], bh + 2 * kk);
                    mma_f16(acc, qh[kk], bl + 2 * kk);
                }
                z0 += __expf(acc[0]) + __expf(acc[1]);
                z1 += __expf(acc[2]) + __expf(acc[3]);
            }
            __syncthreads();
        }

        z0 += __shfl_xor_sync(0xffffffffu, z0, 1);
        z0 += __shfl_xor_sync(0xffffffffu, z0, 2);
        z1 += __shfl_xor_sync(0xffffffffu, z1, 1);
        z1 += __shfl_xor_sync(0xffffffffu, z1, 2);
        const float iz0 = 1.f / z0;
        const float iz1 = 1.f / z1;

        // ================= pass B: attn store + AV, 64-key chunks =========
        float oacc[8][4];
#pragma unroll
        for (int nt = 0; nt < 8; nt++)
#pragma unroll
            for (int q = 0; q < 4; q++) oacc[nt][q] = 0.f;

        float* aA = attn ? attn + ((size_t)(hb * 1024 + row0 + rlA)) * 1024 + 2 * tq
                         : nullptr;
        float* aB = attn ? aA + 8 * 1024 : nullptr;

        prefetchKV64(sb, khi, klo, vhi, 0, t);
        CP_COMMIT();

        for (int ch = 0; ch < 16; ch++) {
            if (ch < 15) {
                prefetchKV64(sb + ((ch + 1) & 1) * ABUF_SZ, khi, klo, vhi,
                             (ch + 1) * 64, t);
                CP_COMMIT();
                CP_WAIT1();
            } else {
                CP_WAIT0();
            }
            __syncthreads();

            const uint32_t kb = sb + (ch & 1) * ABUF_SZ;

#pragma unroll
            for (int grp = 0; grp < 2; grp++) {
                uint32_t ph[2][4];
#pragma unroll
                for (int nt4 = 0; nt4 < 4; nt4++) {
                    int gnt = grp * 4 + nt4;
                    uint32_t addr = kb + (uint32_t)(gnt * 8 * 144) + rowoff;
                    uint32_t bh[8], bl[8];
                    ldsm4(bh,     addr);
                    ldsm4(bh + 4, addr + 64);
                    ldsm4(bl,     addr + B_KLO);
                    ldsm4(bl + 4, addr + B_KLO + 64);
                    float acc[4] = {0.f, 0.f, 0.f, 0.f};
#pragma unroll
                    for (int kk = 0; kk < 4; kk++) {
                        mma_f16(acc, qh[kk], bh + 2 * kk);
                        mma_f16(acc, ql[kk], bh + 2 * kk);
                        mma_f16(acc, qh[kk], bl + 2 * kk);
                    }
                    float e0 = __expf(acc[0]) * iz0;
                    float e1 = __expf(acc[1]) * iz0;
                    float e2 = __expf(acc[2]) * iz1;
                    float e3 = __expf(acc[3]) * iz1;
                    if (aA) {
                        *reinterpret_cast<float2*>(aA + ch * 64 + gnt * 8) =
                            make_float2(e0, e1);
                        *reinterpret_cast<float2*>(aB + ch * 64 + gnt * 8) =
                            make_float2(e2, e3);
                    }
                    int jtl = nt4 >> 1, off = (nt4 & 1) * 2;
                    ph[jtl][off + 0] = pack2h(e0, e1);
                    ph[jtl][off + 1] = pack2h(e2, e3);
                }

                // AV for this 32-key group (single-term P(hi) x V(hi))
#pragma unroll
                for (int nt = 0; nt < 8; nt++) {
                    uint32_t va = kb + B_VHI + (uint32_t)(nt * 8 * 144) +
                                  rowoff + grp * 64;
                    uint32_t vh4[4];
                    ldsm4(vh4, va);
#pragma unroll
                    for (int j = 0; j < 2; j++) {
                        mma_f16(oacc[nt], ph[j], vh4 + 2 * j);
                    }
                }
            }
            __syncthreads();
        }

        // ---- write O ----
        float* oA = out + ((size_t)b * 1024 + row0 + rlA) * 512 + h * 64 + 2 * tq;
        float* oB = oA + 8 * 512;
#pragma unroll
        for (int nt = 0; nt < 8; nt++) {
            *reinterpret_cast<float2*>(oA + 8 * nt) =
                make_float2(oacc[nt][0] * SCALING, oacc[nt][1] * SCALING);
            *reinterpret_cast<float2*>(oB + 8 * nt) =
                make_float2(oacc[nt][2] * SCALING, oacc[nt][3] * SCALING);
        }
    }
}

// ---------------------------------------------------------------------------
extern "C" void kernel_launch(void* const* d_in, const int* in_sizes, int n_in,
                              void* d_out, int out_size)
{
    const float* x  = (const float*)d_in[0];
    const float* Wq = (const float*)d_in[1];
    const float* Wk = (const float*)d_in[2];
    const float* Wv = (const float*)d_in[3];

    const size_t attn_elems = (size_t)Hv * Bv * Nv * Nv;
    float* attn = (float*)d_out;
    float* out  = (float*)d_out + attn_elems;
    if ((size_t)out_size < attn_elems + (size_t)Bv * Nv * Hv * Ev) {
        attn = nullptr;
        out  = (float*)d_out;
    }

    cudaFuncSetAttribute(proj_mma_kernel,
                         cudaFuncAttributeMaxDynamicSharedMemorySize, PROJ_SMEM);
    cudaFuncSetAttribute(attn_mma_kernel,
                         cudaFuncAttributeMaxDynamicSharedMemorySize, ATTN_SMEM);

    split_inputs_kernel<<<2144, 256>>>(x, Wq, Wk, Wv);   // resets attn queue
    proj_mma_kernel<<<dim3(64, 8, 3), 256, PROJ_SMEM>>>();
    attn_mma_kernel<<<296, 256, ATTN_SMEM>>>(attn, out);
}